// round 3
// baseline (speedup 1.0000x reference)
#include <cuda_runtime.h>

#define SQ 1024
#define NB 8
#define NE 512
#define NH 8
#define QHD 32
#define PHD 4
#define PDIM 192
#define NPOS (2*SQ-1)   // 2047
#define INPROJ 544

// Scratch (device globals; no allocations allowed)
__device__ __align__(16) float g_q[NH*NB*SQ*QHD];   // [h][b][s][d]
__device__ __align__(16) float g_k[NH*NB*SQ*QHD];   // [h][b][s][d]
__device__ __align__(16) float g_p[NH*NB*SQ*PHD];   // [h][b][s][d]
__device__ __align__(16) float4 g_pe[NH*NPOS];      // [h][n] (4 dims packed)

// ---------------------------------------------------------------------------
// Kernel 1: proj = x @ W^T + b, scattered into g_q/g_k/g_p layouts.
// M=8192 (m = s*B+b), N=544, K=512. Tile 64x64x16, 256 threads, 4x4/thread.
// ---------------------------------------------------------------------------
__global__ __launch_bounds__(256) void proj_kernel(
    const float* __restrict__ x, const float* __restrict__ w,
    const float* __restrict__ bias)
{
    __shared__ float As[16*68];
    __shared__ float Bs[16*68];
    const int tid = threadIdx.x;
    const int tx = tid & 15, ty = tid >> 4;
    const int m0 = blockIdx.y * 64;
    const int n0 = blockIdx.x * 64;
    const int lrow = tid >> 2;   // 0..63
    const int kq   = tid & 3;    // 0..3 (float4 slot within k-tile)

    float acc[4][4];
#pragma unroll
    for (int i = 0; i < 4; ++i)
#pragma unroll
        for (int j = 0; j < 4; ++j) acc[i][j] = 0.f;

    const float4* xrow = (const float4*)&x[(size_t)(m0 + lrow)*NE];
    const int nw = n0 + lrow;
    const float4* wrow = (nw < INPROJ) ? (const float4*)&w[(size_t)nw*NE] : (const float4*)w;
    const bool wvalid = (nw < INPROJ);

    for (int kt = 0; kt < 32; ++kt) {
        float4 av = xrow[kt*4 + kq];
        float4 bv = make_float4(0.f, 0.f, 0.f, 0.f);
        if (wvalid) bv = wrow[kt*4 + kq];
        __syncthreads();
        As[(4*kq+0)*68 + lrow] = av.x;
        As[(4*kq+1)*68 + lrow] = av.y;
        As[(4*kq+2)*68 + lrow] = av.z;
        As[(4*kq+3)*68 + lrow] = av.w;
        Bs[(4*kq+0)*68 + lrow] = bv.x;
        Bs[(4*kq+1)*68 + lrow] = bv.y;
        Bs[(4*kq+2)*68 + lrow] = bv.z;
        Bs[(4*kq+3)*68 + lrow] = bv.w;
        __syncthreads();
#pragma unroll
        for (int kk = 0; kk < 16; ++kk) {
            float4 a = *(const float4*)&As[kk*68 + 4*ty];
            float4 bb = *(const float4*)&Bs[kk*68 + 4*tx];
            float ar[4] = {a.x, a.y, a.z, a.w};
            float br[4] = {bb.x, bb.y, bb.z, bb.w};
#pragma unroll
            for (int i = 0; i < 4; ++i)
#pragma unroll
                for (int j = 0; j < 4; ++j)
                    acc[i][j] = fmaf(ar[i], br[j], acc[i][j]);
        }
    }

#pragma unroll
    for (int i = 0; i < 4; ++i) {
        int m = m0 + ty*4 + i;
        int s = m >> 3, b = m & 7;
#pragma unroll
        for (int j = 0; j < 4; ++j) {
            int n = n0 + tx*4 + j;
            if (n >= INPROJ) continue;
            float v = acc[i][j] + __ldg(&bias[n]);
            if (n < 256) {
                int h = n >> 5, d = n & 31;
                g_q[(((h<<3)+b)*SQ + s)*QHD + d] = v;
            } else if (n < 512) {
                int n2 = n - 256; int h = n2 >> 5, d = n2 & 31;
                g_k[(((h<<3)+b)*SQ + s)*QHD + d] = v;
            } else {
                int n3 = n - 512; int h = n3 >> 2, d = n3 & 3;
                g_p[(((h<<3)+b)*SQ + s)*PHD + d] = v;
            }
        }
    }
}

// ---------------------------------------------------------------------------
// Kernel 2: g_pe[h][n][0..3] = sum_p pos_emb[n][p] * linear_pos_w[h*4+d][p]
// ---------------------------------------------------------------------------
__global__ __launch_bounds__(256) void pe_kernel(
    const float* __restrict__ pos_emb, const float* __restrict__ lw)
{
    __shared__ float ws[32*193];
    const int tid = threadIdx.x;
    for (int i = tid; i < 32*PDIM; i += 256) {
        int o = i / PDIM, p = i % PDIM;
        ws[o*193 + p] = lw[i];
    }
    __syncthreads();
    int idx = blockIdx.x * 256 + tid;
    if (idx >= NPOS*NH) return;
    int n = idx >> 3, h = idx & 7;
    float a0 = 0.f, a1 = 0.f, a2 = 0.f, a3 = 0.f;
    const float* pr = &pos_emb[(size_t)n*PDIM];
#pragma unroll 4
    for (int p = 0; p < PDIM; ++p) {
        float pv = __ldg(&pr[p]);
        a0 = fmaf(pv, ws[(h*4+0)*193 + p], a0);
        a1 = fmaf(pv, ws[(h*4+1)*193 + p], a1);
        a2 = fmaf(pv, ws[(h*4+2)*193 + p], a2);
        a3 = fmaf(pv, ws[(h*4+3)*193 + p], a3);
    }
    g_pe[h*NPOS + n] = make_float4(a0, a1, a2, a3);
}

// ---------------------------------------------------------------------------
// Kernel 3: fused scores + relative-position shift + mask + softmax + write.
// Block = (q-tile of 16 rows) x (h,b). 256 threads; warp w owns rows 2w,2w+1;
// lane owns j = chunk*128 + jj*32 + lane. Single pass, scores live in regs.
// ---------------------------------------------------------------------------
__device__ __forceinline__ void finish_row(
    float (&a)[32], int lane, int rloc, int qi,
    const float4* pe_s, const float* p_s, const unsigned char* mask_s,
    float* __restrict__ out, int hb)
{
    float p0 = p_s[rloc*4+0], p1 = p_s[rloc*4+1];
    float p2 = p_s[rloc*4+2], p3 = p_s[rloc*4+3];
    float mx = -3.0e38f;
#pragma unroll
    for (int cc = 0; cc < 32; ++cc) {
        int j = (cc >> 2)*128 + (cc & 3)*32 + lane;
        float4 pe = pe_s[j + 15 - rloc];
        float sv = a[cc] + p0*pe.x + p1*pe.y + p2*pe.z + p3*pe.w;
        if (mask_s[j]) sv = -1000.0f;
        a[cc] = sv;
        mx = fmaxf(mx, sv);
    }
#pragma unroll
    for (int o = 16; o; o >>= 1) mx = fmaxf(mx, __shfl_xor_sync(0xffffffffu, mx, o));
    float sum = 0.f;
#pragma unroll
    for (int cc = 0; cc < 32; ++cc) {
        float e = __expf(a[cc] - mx);
        a[cc] = e;
        sum += e;
    }
#pragma unroll
    for (int o = 16; o; o >>= 1) sum += __shfl_xor_sync(0xffffffffu, sum, o);
    float inv = 1.0f / sum;
    float* op = &out[(size_t)(hb*SQ + qi)*SQ];
#pragma unroll
    for (int cc = 0; cc < 32; ++cc) {
        int j = (cc >> 2)*128 + (cc & 3)*32 + lane;
        __stcs(&op[j], a[cc] * inv);   // streaming store: single-use output
    }
}

__global__ __launch_bounds__(256, 2) void attn_kernel(
    const unsigned char* __restrict__ kpm, float* __restrict__ out)
{
    __shared__ float k_s[128*36];         // K chunk [j][d], pad 36: bank-clean
    __shared__ float4 pe_s[1039];         // pe window for this q-tile
    __shared__ float q_s[16*32];
    __shared__ float p_s[16*4];
    __shared__ unsigned char mask_s[SQ];

    const int tid = threadIdx.x;
    const int hb = blockIdx.y;            // h*8 + b
    const int h = hb >> 3, b = hb & 7;
    const int q0 = blockIdx.x * 16;

    for (int i = tid; i < 16*QHD; i += 256) q_s[i] = g_q[((size_t)hb*SQ + q0)*QHD + i];
    for (int i = tid; i < 16*PHD; i += 256) p_s[i] = g_p[((size_t)hb*SQ + q0)*PHD + i];
    const int nlo = 1008 - q0;            // lowest pe index needed
    for (int i = tid; i < 1039; i += 256) pe_s[i] = g_pe[h*NPOS + nlo + i];
    for (int i = tid; i < SQ; i += 256)   mask_s[i] = kpm[b*SQ + i];

    float acc0[32], acc1[32];
#pragma unroll
    for (int i = 0; i < 32; ++i) { acc0[i] = 0.f; acc1[i] = 0.f; }

    const int w = tid >> 5, lane = tid & 31;
    const int r0 = w*2, r1 = w*2 + 1;
    const float4* k4 = (const float4*)g_k + (size_t)hb*SQ*8;

#pragma unroll
    for (int c = 0; c < 8; ++c) {
        __syncthreads();
        // load K chunk (128 rows of 32 floats) into k_s, conflict-free
        for (int f = tid; f < 1024; f += 256) {
            int j = f >> 3, d4 = f & 7;
            float4 kv = __ldg(&k4[(size_t)(c*128 + j)*8 + d4]);
            *(float4*)&k_s[j*36 + d4*4] = kv;
        }
        __syncthreads();
#pragma unroll 2
        for (int kk4 = 0; kk4 < 8; ++kk4) {
            float4 qa = *(const float4*)&q_s[r0*32 + kk4*4];
            float4 qb = *(const float4*)&q_s[r1*32 + kk4*4];
#pragma unroll
            for (int jj = 0; jj < 4; ++jj) {
                int jl = jj*32 + lane;
                float4 kv = *(const float4*)&k_s[jl*36 + kk4*4];
                int cc = c*4 + jj;
                acc0[cc] += qa.x*kv.x + qa.y*kv.y + qa.z*kv.z + qa.w*kv.w;
                acc1[cc] += qb.x*kv.x + qb.y*kv.y + qb.z*kv.z + qb.w*kv.w;
            }
        }
    }

    finish_row(acc0, lane, r0, q0 + r0, pe_s, p_s, mask_s, out, hb);
    finish_row(acc1, lane, r1, q0 + r1, pe_s, p_s, mask_s, out, hb);
}

// ---------------------------------------------------------------------------
extern "C" void kernel_launch(void* const* d_in, const int* in_sizes, int n_in,
                              void* d_out, int out_size)
{
    const float* x            = (const float*)d_in[0];          // (S,B,E)
    const float* pos_emb      = (const float*)d_in[1];          // (1,2S-1,PDIM)
    const unsigned char* kpm  = (const unsigned char*)d_in[2];  // (B,S) bool
    const float* in_proj_w    = (const float*)d_in[3];          // (544,512)
    const float* in_proj_b    = (const float*)d_in[4];          // (544,)
    const float* linear_pos_w = (const float*)d_in[5];          // (32,192)
    float* out = (float*)d_out;                                 // (H,B,S,S)

    dim3 g1((INPROJ + 63)/64, (SQ*NB)/64);   // 9 x 128
    proj_kernel<<<g1, 256>>>(x, in_proj_w, in_proj_b);

    pe_kernel<<<(NPOS*NH + 255)/256, 256>>>(pos_emb, linear_pos_w);

    dim3 g3(SQ/16, NH*NB);                   // 64 x 64
    attn_kernel<<<g3, 256>>>(kpm, out);
}